// round 17
// baseline (speedup 1.0000x reference)
#include <cuda_runtime.h>
#include <cuda_bf16.h>
#include <mma.h>
#include <cstddef>

using namespace nvcuda;

#define N_NODES 50000
#define N_EDGES 800000
#define D_IN    128
#define D_HID   256
#define D_OUT   128
#define NBLK    49          // ceil(N_NODES / 1024)

// ---------------- device scratch (static, allocation-free) ----------------
__device__ int   g_is64;
__device__ int   g_cnt[N_NODES];
__device__ int   g_rowstart[N_NODES + 1];
__device__ int   g_work[N_NODES];
__device__ int   g_csr_src[N_EDGES];
__device__ int   g_blocksum[NBLK];
__device__ float g_z[(size_t)N_NODES * D_IN];  // layer1 agg; reused as z = h@W2_l
__device__ float g_h[(size_t)N_NODES * D_HID];

// ---------------- CSR build ----------------
__global__ void zero_cnt_k(const int* __restrict__ ei32) {
    int i = blockIdx.x * blockDim.x + threadIdx.x;
    if (i < N_NODES) g_cnt[i] = 0;
    if (i == 0) {
        int is64 = 1;
        #pragma unroll
        for (int j = 1; j < 64; j += 2)
            if (ei32[j] != 0) is64 = 0;
        g_is64 = is64;
    }
}

__device__ __forceinline__ int load_edge(const void* ei, size_t idx, int is64) {
    if (is64) return (int)((const long long*)ei)[idx];
    return ((const int*)ei)[idx];
}

__global__ void count_k(const void* __restrict__ ei) {
    int i = blockIdx.x * blockDim.x + threadIdx.x;
    if (i < N_EDGES) {
        int is64 = g_is64;
        int d = load_edge(ei, (size_t)N_EDGES + i, is64);
        if ((unsigned)d < (unsigned)N_NODES) atomicAdd(&g_cnt[d], 1);
    }
}

__global__ __launch_bounds__(1024) void scan_a_k() {
    __shared__ int wsum[32];
    int t = threadIdx.x, lane = t & 31, wid = t >> 5;
    int i = blockIdx.x * 1024 + t;
    int v = (i < N_NODES) ? g_cnt[i] : 0;
    #pragma unroll
    for (int off = 16; off > 0; off >>= 1)
        v += __shfl_down_sync(0xffffffffu, v, off);
    if (lane == 0) wsum[wid] = v;
    __syncthreads();
    if (wid == 0) {
        int w = wsum[lane];
        #pragma unroll
        for (int off = 16; off > 0; off >>= 1)
            w += __shfl_down_sync(0xffffffffu, w, off);
        if (lane == 0) g_blocksum[blockIdx.x] = w;
    }
}

__global__ __launch_bounds__(1024) void scan_c_k() {
    __shared__ int wsum[32];
    __shared__ int blk_off, total_sh;
    int t = threadIdx.x, lane = t & 31, wid = t >> 5;
    int bid = blockIdx.x;

    if (wid == 0) {
        int s0 = (lane < NBLK) ? g_blocksum[lane] : 0;
        int s1 = (lane + 32 < NBLK) ? g_blocksum[lane + 32] : 0;
        int pre = ((lane < bid) ? s0 : 0) + ((lane + 32 < bid) ? s1 : 0);
        int tot = s0 + s1;
        #pragma unroll
        for (int off = 16; off > 0; off >>= 1) {
            pre += __shfl_down_sync(0xffffffffu, pre, off);
            tot += __shfl_down_sync(0xffffffffu, tot, off);
        }
        if (lane == 0) { blk_off = pre; total_sh = tot; }
    }

    int i = bid * 1024 + t;
    int v = (i < N_NODES) ? g_cnt[i] : 0;

    int inc = v;
    #pragma unroll
    for (int off = 1; off < 32; off <<= 1) {
        int u = __shfl_up_sync(0xffffffffu, inc, off);
        if (lane >= off) inc += u;
    }
    if (lane == 31) wsum[wid] = inc;
    __syncthreads();
    if (wid == 0) {
        int w = wsum[lane];
        #pragma unroll
        for (int off = 1; off < 32; off <<= 1) {
            int u = __shfl_up_sync(0xffffffffu, w, off);
            if (lane >= off) w += u;
        }
        wsum[lane] = w;
    }
    __syncthreads();

    int excl = inc - v + (wid > 0 ? wsum[wid - 1] : 0) + blk_off;
    if (i < N_NODES) {
        g_rowstart[i] = excl;
        g_work[i]     = excl;
    }
    if (bid == 0 && t == 0) g_rowstart[N_NODES] = total_sh;
}

__global__ void place_k(const void* __restrict__ ei) {
    int i = blockIdx.x * blockDim.x + threadIdx.x;
    if (i < N_EDGES) {
        int is64 = g_is64;
        int s = load_edge(ei, (size_t)i, is64);
        int d = load_edge(ei, (size_t)N_EDGES + i, is64);
        if ((unsigned)d < (unsigned)N_NODES && (unsigned)s < (unsigned)N_NODES) {
            int pos = atomicAdd(&g_work[d], 1);
            g_csr_src[pos] = s;
        }
    }
}

// ---------------- gather-mean: one warp per destination node (F=128) ----------------
template <int ADD>
__device__ __forceinline__ void gather128_body(const float* __restrict__ feat,
                                               float* __restrict__ agg) {
    int warp = (blockIdx.x * blockDim.x + threadIdx.x) >> 5;
    int lane = threadIdx.x & 31;
    if (warp >= N_NODES) return;
    int beg = g_rowstart[warp], end = g_rowstart[warp + 1];
    float4 acc = make_float4(0.f, 0.f, 0.f, 0.f);

    int e = beg;
    for (; e + 4 <= end; e += 4) {
        int s0 = g_csr_src[e + 0];
        int s1 = g_csr_src[e + 1];
        int s2 = g_csr_src[e + 2];
        int s3 = g_csr_src[e + 3];
        float4 v0 = ((const float4*)(feat + (size_t)s0 * 128))[lane];
        float4 v1 = ((const float4*)(feat + (size_t)s1 * 128))[lane];
        float4 v2 = ((const float4*)(feat + (size_t)s2 * 128))[lane];
        float4 v3 = ((const float4*)(feat + (size_t)s3 * 128))[lane];
        acc.x += v0.x + v1.x + v2.x + v3.x;
        acc.y += v0.y + v1.y + v2.y + v3.y;
        acc.z += v0.z + v1.z + v2.z + v3.z;
        acc.w += v0.w + v1.w + v2.w + v3.w;
    }
    for (; e < end; e++) {
        int s = g_csr_src[e];
        float4 v = ((const float4*)(feat + (size_t)s * 128))[lane];
        acc.x += v.x; acc.y += v.y; acc.z += v.z; acc.w += v.w;
    }

    int deg = end - beg;
    float scale = 1.0f / (float)(deg > 0 ? deg : 1);
    float4* o = (float4*)(agg + (size_t)warp * 128);
    float4 r;
    if (ADD) {
        float4 prev = o[lane];
        r.x = prev.x + acc.x * scale; r.y = prev.y + acc.y * scale;
        r.z = prev.z + acc.z * scale; r.w = prev.w + acc.w * scale;
    } else {
        r.x = acc.x * scale; r.y = acc.y * scale;
        r.z = acc.z * scale; r.w = acc.w * scale;
    }
    o[lane] = r;
}

__global__ void gather_x_to_z_k(const float* __restrict__ x) {
    gather128_body<0>(x, g_z);
}
__global__ void gather_z_add_out_k(float* __restrict__ out) {
    gather128_body<1>(g_z, out);
}

// ---------------- tf32 wmma GEMM, BK=32, double-buffered (1 barrier/tile) ----
// MODE 1 (layer 1): O0[N,256] = relu([A0 | A1] @ [W0 ; W1] + bias)
// MODE 2 (layer 2): [O0 | O1] = A @ [W0 | W1]; O0 = g_z, O1 = out (+bias)
// BM=128, BN=64, BK=32; 8 warps (4x2), warp tile 32x32 (2x2 wmma 16x16x8).
// tf32 conversion happens ONCE at commit; fragment loads use data directly.
#define KTOT 256
#define BKT  32
#define LDA  36     // 32 + 4 pad
#define LDB  68     // 64 + 4 pad
#define LDS_ 36

template <int MODE>
__device__ __forceinline__ void wmma_gemm_body(
    const float* __restrict__ A0, const float* __restrict__ A1,
    int sa0, int sa1,
    const float* __restrict__ W0, const float* __restrict__ W1,
    const float* __restrict__ bias,
    float* __restrict__ O0, float* __restrict__ O1)
{
    __shared__ float smem[13568];          // 54,272 B
    float* sA[2] = { smem, smem + 128 * LDA };                  // 2 x 4608
    float* sB[2] = { smem + 2 * 128 * LDA, smem + 2 * 128 * LDA + BKT * LDB }; // 2 x 2176

    const int tid  = threadIdx.x;
    const int lane = tid & 31;
    const int wid  = tid >> 5;
    const int wm   = wid & 3;
    const int wn   = wid >> 2;
    const int row0 = blockIdx.y * 128;
    const int col0 = blockIdx.x * 64;

    // A loader: 128 rows x 32 k / 256 thr -> 16 floats each
    const int lr = tid >> 1;               // 0..127
    const int lk = (tid & 1) * 16;         // 0 or 16
    // B loader: 32 k x 64 cols / 256 thr -> 8 floats each
    const int bk = tid >> 3;               // 0..31
    const int bc = (tid & 7) * 8;          // 0,8,..,56

    const int grow_a = row0 + lr;
    const bool arow_ok = (grow_a < N_NODES);

    wmma::fragment<wmma::accumulator, 16, 16, 8, float> acc[2][2];
    #pragma unroll
    for (int i = 0; i < 2; i++)
        #pragma unroll
        for (int j = 0; j < 2; j++)
            wmma::fill_fragment(acc[i][j], 0.0f);

    float4 ra[4], rb[2];
    auto fetch = [&](int k0) {
        #pragma unroll
        for (int q = 0; q < 4; q++) ra[q] = make_float4(0.f, 0.f, 0.f, 0.f);
        int gk = k0 + lk;   // 16-aligned; chunk of 16 stays within one half
        if (arow_ok) {
            const float* src = (gk < 128)
                ? A0 + (size_t)grow_a * sa0 + gk
                : A1 + (size_t)grow_a * sa1 + (gk - 128);
            #pragma unroll
            for (int q = 0; q < 4; q++) ra[q] = *(const float4*)(src + q * 4);
        }
        int gkb = k0 + bk;
        int gc  = col0 + bc; // 8-aligned; chunk of 8 stays within one half
        const float* wsrc;
        if (MODE == 1) {
            wsrc = (gkb < 128) ? W0 + (size_t)gkb * 256 + gc
                               : W1 + (size_t)(gkb - 128) * 256 + gc;
        } else {
            wsrc = (gc < 128) ? W0 + (size_t)gkb * 128 + gc
                              : W1 + (size_t)gkb * 128 + (gc - 128);
        }
        rb[0] = *(const float4*)(wsrc);
        rb[1] = *(const float4*)(wsrc + 4);
    };
    auto cvt4 = [](float4 v) {
        v.x = wmma::__float_to_tf32(v.x); v.y = wmma::__float_to_tf32(v.y);
        v.z = wmma::__float_to_tf32(v.z); v.w = wmma::__float_to_tf32(v.w);
        return v;
    };
    auto commit = [&](int buf) {
        float* d = &sA[buf][lr * LDA + lk];
        #pragma unroll
        for (int q = 0; q < 4; q++) {
            float4 v = cvt4(ra[q]);
            d[q * 4 + 0] = v.x; d[q * 4 + 1] = v.y;
            d[q * 4 + 2] = v.z; d[q * 4 + 3] = v.w;
        }
        float* db = &sB[buf][bk * LDB + bc];
        float4 w0 = cvt4(rb[0]), w1 = cvt4(rb[1]);
        *(float4*)(db)     = w0;
        *(float4*)(db + 4) = w1;
    };

    fetch(0);
    commit(0);
    __syncthreads();

    const int NT = KTOT / BKT;  // 8 tiles
    for (int t = 0; t < NT; t++) {
        int cur = t & 1;
        if (t + 1 < NT) fetch((t + 1) * BKT);

        #pragma unroll
        for (int kk8 = 0; kk8 < BKT; kk8 += 8) {
            wmma::fragment<wmma::matrix_a, 16, 16, 8, wmma::precision::tf32, wmma::row_major> af[2];
            wmma::fragment<wmma::matrix_b, 16, 16, 8, wmma::precision::tf32, wmma::row_major> bf[2];
            #pragma unroll
            for (int i = 0; i < 2; i++)
                wmma::load_matrix_sync(af[i], &sA[cur][(wm * 32 + i * 16) * LDA + kk8], LDA);
            #pragma unroll
            for (int j = 0; j < 2; j++)
                wmma::load_matrix_sync(bf[j], &sB[cur][kk8 * LDB + wn * 32 + j * 16], LDB);
            #pragma unroll
            for (int i = 0; i < 2; i++)
                #pragma unroll
                for (int j = 0; j < 2; j++)
                    wmma::mma_sync(acc[i][j], af[i], bf[j], acc[i][j]);
        }

        if (t + 1 < NT) commit((t + 1) & 1);
        __syncthreads();
    }

    // ---- epilogue: stage warp tile 32x32 in smem, then coalesced global write ----
    float* stg = smem + wid * 32 * LDS_;
    #pragma unroll
    for (int i = 0; i < 2; i++)
        #pragma unroll
        for (int j = 0; j < 2; j++)
            wmma::store_matrix_sync(&stg[(i * 16) * LDS_ + j * 16], acc[i][j],
                                    LDS_, wmma::mem_row_major);
    __syncwarp();

    int grow = row0 + wm * 32 + lane;
    if (grow < N_NODES) {
        int gcol0 = col0 + wn * 32;
        #pragma unroll
        for (int c4 = 0; c4 < 8; c4++) {
            float4 v = *(float4*)&stg[lane * LDS_ + c4 * 4];
            int gc = gcol0 + c4 * 4;
            if (MODE == 1) {
                v.x += bias[gc + 0]; v.y += bias[gc + 1];
                v.z += bias[gc + 2]; v.w += bias[gc + 3];
                v.x = fmaxf(v.x, 0.f); v.y = fmaxf(v.y, 0.f);
                v.z = fmaxf(v.z, 0.f); v.w = fmaxf(v.w, 0.f);
                *(float4*)(O0 + (size_t)grow * 256 + gc) = v;
            } else {
                if (gc < 128) {
                    *(float4*)(O0 + (size_t)grow * 128 + gc) = v;
                } else {
                    int c = gc - 128;
                    v.x += bias[c + 0]; v.y += bias[c + 1];
                    v.z += bias[c + 2]; v.w += bias[c + 3];
                    *(float4*)(O1 + (size_t)grow * 128 + c) = v;
                }
            }
        }
    }
}

// wrappers binding scratch symbols on the device side
__global__ __launch_bounds__(256) void gemm1_k(
    const float* __restrict__ x, const float* __restrict__ W1l,
    const float* __restrict__ W1r, const float* __restrict__ b1)
{
    wmma_gemm_body<1>(g_z, x, D_IN, D_IN, W1l, W1r, b1, g_h, nullptr);
}

__global__ __launch_bounds__(256) void gemm2_k(
    const float* __restrict__ W2l, const float* __restrict__ W2r,
    const float* __restrict__ b2, float* __restrict__ out)
{
    wmma_gemm_body<2>(g_h, g_h + 128, D_HID, D_HID, W2l, W2r, b2, g_z, out);
}

// ---------------- launch ----------------
extern "C" void kernel_launch(void* const* d_in, const int* in_sizes, int n_in,
                              void* d_out, int out_size) {
    const float* x   = (const float*)d_in[0];
    const void*  ei  = d_in[1];                 // int32 or int64; detected at runtime
    const float* W1l = (const float*)d_in[2];
    const float* b1  = (const float*)d_in[3];
    const float* W1r = (const float*)d_in[4];
    const float* W2l = (const float*)d_in[5];
    const float* b2  = (const float*)d_in[6];
    const float* W2r = (const float*)d_in[7];
    float*       out = (float*)d_out;

    // CSR build (per launch; deterministic)
    zero_cnt_k<<<(N_NODES + 255) / 256, 256>>>((const int*)ei);
    count_k<<<(N_EDGES + 255) / 256, 256>>>(ei);
    scan_a_k<<<NBLK, 1024>>>();
    scan_c_k<<<NBLK, 1024>>>();
    place_k<<<(N_EDGES + 255) / 256, 256>>>(ei);

    const int gather_blocks = (N_NODES * 32 + 255) / 256;
    const dim3 gg(256 / 64, (N_NODES + 127) / 128);   // 4 x 391

    // Layer 1: g_z = mean_agg(x) ; g_h = relu([g_z|x]@[W1l;W1r] + b1)
    gather_x_to_z_k<<<gather_blocks, 256>>>(x);
    gemm1_k<<<gg, 256>>>(x, W1l, W1r, b1);

    // Layer 2: [g_z | out] = g_h@[W2l | W2r] (+b2 on out) ; out += mean_agg(g_z)
    gemm2_k<<<gg, 256>>>(W2l, W2r, b2, out);
    gather_z_add_out_k<<<gather_blocks, 256>>>(out);
}